// round 1
// baseline (speedup 1.0000x reference)
#include <cuda_runtime.h>
#include <math.h>

#define MM 63
#define NN 127
#define BB 256
#define MAXC 96
#define OUT_LOSS (4*BB*NN)

__device__ unsigned char g_cols[MM][MAXC];
__device__ int g_cnt[MM];
__device__ float g_sp;

// Parse H into per-check column lists, compute softplus(check_weight), zero loss slot.
__global__ void setup_kernel(const float* __restrict__ H,
                             const float* __restrict__ cw,
                             float* __restrict__ out) {
    int m = threadIdx.x;
    if (m < MM) {
        int cnt = 0;
        for (int n = 0; n < NN; ++n) {
            if (H[m * NN + n] != 0.0f) {
                if (cnt < MAXC) g_cols[m][cnt] = (unsigned char)n;
                ++cnt;
            }
        }
        g_cnt[m] = (cnt < MAXC) ? cnt : MAXC;
    }
    if (m == 0) {
        float x = cw[0];
        g_sp = (x > 0.f) ? (x + log1pf(expf(-x))) : log1pf(expf(x));
        out[OUT_LOSS] = 0.0f;
    }
}

__global__ __launch_bounds__(512)
void decode_kernel(const float* __restrict__ soft_in,
                   const int*   __restrict__ labels,
                   float*       __restrict__ out) {
    __shared__ float s_soft[NN];
    __shared__ float s_acc[NN + 1];
    __shared__ unsigned char s_cols[MM][MAXC];
    __shared__ int s_cnt[MM];
    __shared__ float s_red[16];

    const int b   = blockIdx.x;
    const int tid = threadIdx.x;
    const int bd  = blockDim.x;

    // Load soft row into shared; emit outs[0] = soft_input.
    for (int n = tid; n < NN; n += bd) {
        float v = soft_in[b * NN + n];
        s_soft[n] = v;
        out[b * NN + n] = v;
    }
    // Stage H structure in shared (read many times).
    for (int i = tid; i < MM * MAXC; i += bd)
        ((unsigned char*)s_cols)[i] = ((const unsigned char*)g_cols)[i];
    for (int i = tid; i < MM; i += bd)
        s_cnt[i] = g_cnt[i];
    __syncthreads();

    const float sp = g_sp;

    // 8 distinct variant rows: variant v in {0=identity, 1=split==perm (x2 weight)},
    // shift s in {0,31,62,93}. sigma_t(c) = e_v((c - s) mod 127).
    int task = -1, m = 0, v = 0, sh = 0;
    float coef = 0.f;
    if (tid < 8 * MM) {
        task = tid / MM;
        m    = tid - task * MM;
        v    = task >> 2;
        sh   = (task & 3) * 31;
        coef = sp * (v ? 2.0f : 1.0f);
    }
    const int cnt = (task >= 0) ? s_cnt[m] : 0;

    for (int it = 0; it < 3; ++it) {
        for (int n = tid; n < NN; n += bd) s_acc[n] = 0.f;
        __syncthreads();

        if (task >= 0) {
            float min1 = 1e38f, min2 = 1e38f, sg = 1.f;
            // Pass 1: sign product + two smallest magnitudes over this check's columns.
            #pragma unroll 4
            for (int i = 0; i < cnt; ++i) {
                int c = s_cols[m][i];
                int j = c - sh; if (j < 0) j += NN;
                int idx = v ? ((2 * j >= NN) ? 2 * j - NN : 2 * j) : j;
                float y = s_soft[idx];
                float a = fabsf(y);
                float s1 = (y > 0.f) ? 1.f : ((y < 0.f) ? -1.f : 0.f);
                sg *= s1;
                if (a < min1) { min2 = min1; min1 = a; }
                else if (a < min2) { min2 = a; }
            }
            float base1 = coef * sg * min1;
            float base2 = coef * sg * min2;
            // Pass 2: scatter messages back through the same permutation.
            #pragma unroll 4
            for (int i = 0; i < cnt; ++i) {
                int c = s_cols[m][i];
                int j = c - sh; if (j < 0) j += NN;
                int idx = v ? ((2 * j >= NN) ? 2 * j - NN : 2 * j) : j;
                float y = s_soft[idx];
                float a = fabsf(y);
                float s1 = (y > 0.f) ? 1.f : ((y < 0.f) ? -1.f : 0.f);
                float msg = ((a > min1) ? base1 : base2) * s1;
                atomicAdd(&s_acc[idx], msg);
            }
        }
        __syncthreads();

        for (int n = tid; n < NN; n += bd) {
            float ns = s_soft[n] + s_acc[n] * (1.0f / 12.0f);
            s_soft[n] = ns;
            out[(it + 1) * BB * NN + b * NN + n] = ns;
        }
        __syncthreads();
    }

    // Loss on final soft (reference overwrites loss each iteration; last one survives).
    float part = 0.f;
    for (int n = tid; n < NN; n += bd) {
        float x  = s_soft[n];
        float lf = (float)labels[b * NN + n];
        float sgn = (x > 0.f) ? 1.f : ((x < 0.f) ? -1.f : 0.f);
        float tgt = 1.f - 2.f * lf;
        float w   = (sgn != tgt) ? 2.0f : 1.0f;
        float z   = -x;
        float ce  = fmaxf(z, 0.f) - z * lf + log1pf(expf(-fabsf(z)));
        part += w * ce;
    }
    #pragma unroll
    for (int off = 16; off; off >>= 1)
        part += __shfl_down_sync(0xffffffffu, part, off);
    if ((tid & 31) == 0) s_red[tid >> 5] = part;
    __syncthreads();
    if (tid < 16) {
        part = s_red[tid];
        #pragma unroll
        for (int off = 8; off; off >>= 1)
            part += __shfl_down_sync(0xffffu, part, off);
        if (tid == 0) atomicAdd(&out[OUT_LOSS], part);
    }
}

extern "C" void kernel_launch(void* const* d_in, const int* in_sizes, int n_in,
                              void* d_out, int out_size) {
    const float* soft = (const float*)d_in[0];
    const int*   lab  = (const int*)d_in[1];
    const float* H    = (const float*)d_in[2];
    const float* cw   = (const float*)d_in[3];
    float* out = (float*)d_out;

    setup_kernel<<<1, 64>>>(H, cw, out);
    decode_kernel<<<BB, 512>>>(soft, lab, out);
}

// round 2
// speedup vs baseline: 1.6410x; 1.6410x over previous
#include <cuda_runtime.h>
#include <math.h>

#define MM 63
#define NN 127
#define BB 256
#define OUT_LOSS (4*BB*NN)
#define MAXC 64          // max row weight (expected ~52)
#define MAXR 40          // max column weight (expected ~34)
#define NI4  (MAXC/4)    // 16 packed words per job
#define NJ4  (MAXR/4)    // 10 packed words per column

// Precomputed structure (built once by setup_kernel):
// g_idx4[i4*512 + jid]: 4 packed pre-permuted column indices (sigma_t applied) for job jid=(t,m). pad=127
// g_cnt4[m]           : ceil(row_weight/4)
// g_rows4[j4*NN + c]  : 4 packed check indices m with H[m][c]=1. pad=63
// g_ccnt4[c]          : ceil(col_weight/4)
__device__ unsigned g_idx4[NI4 * 512];
__device__ int      g_cnt4[MM];
__device__ unsigned g_rows4[NJ4 * NN];
__device__ int      g_ccnt4[NN];
__device__ float    g_sp;

__global__ void setup_kernel(const float* __restrict__ H,
                             const float* __restrict__ cw,
                             float* __restrict__ out) {
    int tid = threadIdx.x;
    if (tid < 504) {
        int t = tid / MM, m = tid - t * MM;
        int v = t >> 2, sh = (t & 3) * 31;
        unsigned char cols[MAXC];
        int cnt = 0;
        for (int n = 0; n < NN; ++n)
            if (H[m * NN + n] != 0.0f && cnt < MAXC) cols[cnt++] = (unsigned char)n;
        if (t == 0) g_cnt4[m] = (cnt + 3) >> 2;
        for (int i4 = 0; i4 < NI4; ++i4) {
            unsigned w = 0;
            for (int k = 0; k < 4; ++k) {
                int i = i4 * 4 + k;
                int idx = NN;  // pad slot -> s_soft[127] = +huge
                if (i < cnt) {
                    int j = (int)cols[i] - sh; if (j < 0) j += NN;
                    idx = v ? ((2 * j >= NN) ? 2 * j - NN : 2 * j) : j;
                }
                w |= (unsigned)idx << (8 * k);
            }
            g_idx4[i4 * 512 + tid] = w;
        }
    }
    if (tid < NN) {
        int c = tid;
        unsigned char rows[MAXR];
        int rc = 0;
        for (int m = 0; m < MM; ++m)
            if (H[m * NN + c] != 0.0f && rc < MAXR) rows[rc++] = (unsigned char)m;
        g_ccnt4[c] = (rc + 3) >> 2;
        for (int j4 = 0; j4 < NJ4; ++j4) {
            unsigned w = 0;
            for (int k = 0; k < 4; ++k) {
                int j = j4 * 4 + k;
                int mm = (j < rc) ? (int)rows[j] : MM;  // pad -> dummy stats slot 63
                w |= (unsigned)mm << (8 * k);
            }
            g_rows4[j4 * NN + c] = w;
        }
    }
    if (tid == 0) {
        float x = cw[0];
        g_sp = (x > 0.f) ? (x + log1pf(expf(-x))) : log1pf(expf(x));
        out[OUT_LOSS] = 0.0f;
    }
}

__global__ __launch_bounds__(512)
void decode_kernel(const float* __restrict__ soft_in,
                   const int*   __restrict__ labels,
                   float*       __restrict__ out) {
    __shared__ float    s_soft[NN + 1];      // slot 127 = +huge (padding)
    __shared__ float4   s_stats[8 * 64];     // [t][m], m=63 dummy
    __shared__ unsigned s_rows4[NJ4 * NN];
    __shared__ int      s_ccnt4[NN];
    __shared__ float    s_red[16];

    const int b   = blockIdx.x;
    const int tid = threadIdx.x;

    // --- staging ---
    for (int n = tid; n < NN; n += 512) {
        float v = soft_in[b * NN + n];
        s_soft[n] = v;
        out[b * NN + n] = v;               // outs[0]
    }
    if (tid == 0) s_soft[NN] = 1e38f;
    for (int i = tid; i < NJ4 * NN; i += 512) s_rows4[i] = g_rows4[i];
    for (int i = tid; i < NN; i += 512)       s_ccnt4[i] = g_ccnt4[i];
    // dummy stats for padded check index 63 (min1=-1 -> always picks base1=0)
    if (tid >= 504) s_stats[(tid - 504) * 64 + MM] = make_float4(-1.f, 0.f, 0.f, 0.f);

    // Phase-A job identity
    const int  t_a    = tid / MM;
    const int  m_a    = tid - t_a * MM;
    const bool validA = (tid < 504);
    const float coefA = validA ? (g_sp * ((t_a >> 2) ? 2.0f : 1.0f)) : 0.f;
    const int  cnt4   = validA ? g_cnt4[m_a] : 0;

    // Phase-B job identity: t = tid&7, base n = tid>>3
    const int t_b  = tid & 7;
    const int v_b  = t_b >> 2;
    const int sh_b = (t_b & 3) * 31;
    const int n_b0 = tid >> 3;

    __syncthreads();

    for (int it = 0; it < 3; ++it) {
        // ---------- Phase A: per-check min1/min2/sign ----------
        if (validA) {
            float min1 = 1e38f, min2 = 1e38f;
            unsigned sgbit = 0u;
            bool zero = false;
            #pragma unroll 4
            for (int i4 = 0; i4 < cnt4; ++i4) {
                unsigned w = g_idx4[i4 * 512 + tid];
                #pragma unroll
                for (int k = 0; k < 4; ++k) {
                    int idx = (w >> (8 * k)) & 255;
                    float y = s_soft[idx];
                    sgbit ^= __float_as_uint(y) & 0x80000000u;
                    zero |= (y == 0.0f);
                    float a  = fabsf(y);
                    float lo = fminf(a, min1);
                    min2 = fminf(min2, fmaxf(a, min1));
                    min1 = lo;
                }
            }
            float sg = zero ? 0.f : (sgbit ? -1.f : 1.f);
            float cs = coefA * sg;
            s_stats[t_a * 64 + m_a] = make_float4(min1, cs * min1, cs * min2, 0.f);
        }
        __syncthreads();

        // ---------- Phase B: gather messages per variable ----------
        float accR[2];
        #pragma unroll
        for (int r = 0; r < 2; ++r) {
            int n = n_b0 + r * 64;
            float acc = 0.f;
            if (n < NN) {
                int cb = v_b ? ((n * 64) % NN) : n;     // inverse permutation
                int c  = cb + sh_b; if (c >= NN) c -= NN;
                float y  = s_soft[n];
                float a  = fabsf(y);
                int   cc4 = s_ccnt4[c];
                float sum = 0.f;
                #pragma unroll 2
                for (int j4 = 0; j4 < cc4; ++j4) {
                    unsigned w = s_rows4[j4 * NN + c];
                    #pragma unroll
                    for (int k = 0; k < 4; ++k) {
                        int m = (w >> (8 * k)) & 255;
                        float4 st = s_stats[t_b * 64 + m];
                        sum += (a > st.x) ? st.y : st.z;
                    }
                }
                float s1 = (y > 0.f) ? 1.f : ((y < 0.f) ? -1.f : 0.f);
                acc = s1 * sum;
            }
            acc += __shfl_xor_sync(0xffffffffu, acc, 1);
            acc += __shfl_xor_sync(0xffffffffu, acc, 2);
            acc += __shfl_xor_sync(0xffffffffu, acc, 4);
            accR[r] = acc;
        }
        __syncthreads();   // all s_soft reads complete

        if (t_b == 0) {
            #pragma unroll
            for (int r = 0; r < 2; ++r) {
                int n = n_b0 + r * 64;
                if (n < NN) s_soft[n] += accR[r] * (1.0f / 12.0f);
            }
        }
        __syncthreads();

        for (int n = tid; n < NN; n += 512)
            out[(it + 1) * BB * NN + b * NN + n] = s_soft[n];
        __syncthreads();
    }

    // ---------- loss on final soft ----------
    float part = 0.f;
    for (int n = tid; n < NN; n += 512) {
        float x   = s_soft[n];
        float lf  = (float)labels[b * NN + n];
        float sgn = (x > 0.f) ? 1.f : ((x < 0.f) ? -1.f : 0.f);
        float w   = (sgn != 1.f - 2.f * lf) ? 2.0f : 1.0f;
        float z   = -x;
        float ce  = fmaxf(z, 0.f) - z * lf + log1pf(expf(-fabsf(z)));
        part += w * ce;
    }
    #pragma unroll
    for (int off = 16; off; off >>= 1)
        part += __shfl_down_sync(0xffffffffu, part, off);
    if ((tid & 31) == 0) s_red[tid >> 5] = part;
    __syncthreads();
    if (tid < 16) {
        part = s_red[tid];
        #pragma unroll
        for (int off = 8; off; off >>= 1)
            part += __shfl_down_sync(0xffffu, part, off);
        if (tid == 0) atomicAdd(&out[OUT_LOSS], part);
    }
}

extern "C" void kernel_launch(void* const* d_in, const int* in_sizes, int n_in,
                              void* d_out, int out_size) {
    const float* soft = (const float*)d_in[0];
    const int*   lab  = (const int*)d_in[1];
    const float* H    = (const float*)d_in[2];
    const float* cw   = (const float*)d_in[3];
    float* out = (float*)d_out;

    setup_kernel<<<1, 512>>>(H, cw, out);
    decode_kernel<<<BB, 512>>>(soft, lab, out);
}